// round 1
// baseline (speedup 1.0000x reference)
#include <cuda_runtime.h>
#include <cuda_bf16.h>
#include <cstdint>

// Problem shape (fixed): v (B=4, S=2048, H=12, D=64) f32, w (H=12, S=2048) f32.
// seq_len = 2046 (valid l,j in [1,2046]).
// pbv[n,j,h,d] = sum_{l=1}^{2046} w[h,|l-j|] * v[n,l,h,d]   (0 for j in {0,2047})
// z_pb[j,h]    = w[h,0] + P[j-1] + P[2046-j],  P[t]=sum_{m=1}^{t} w[h,m]  (0 for j in {0,2047})
// Output layout: pbv (4*2048*12*64 floats) followed by z_pb (2048*12 floats).

#define B_ 4
#define S_ 2048
#define H_ 12
#define D_ 64
#define TJ 128
#define TL 64

__device__ __forceinline__ unsigned long long ffma2(unsigned long long a,
                                                    unsigned long long b,
                                                    unsigned long long c) {
    unsigned long long d;
    asm("fma.rn.f32x2 %0, %1, %2, %3;" : "=l"(d) : "l"(a), "l"(b), "l"(c));
    return d;
}

__global__ void __launch_bounds__(256) pbv_kernel(
    const float* __restrict__ v, const float* __restrict__ w,
    float* __restrict__ out)
{
    const int jt = blockIdx.x;   // 0..15
    const int h  = blockIdx.y;   // 0..11
    const int n  = blockIdx.z;   // 0..3
    const int j0 = jt * TJ;

    __shared__ float2 wdup[2048];          // wdup[m] = (w[h,m], w[h,m]); 0 for m>=2046
    __shared__ float  vtile[TL][64];

    const int tid = threadIdx.x;

    // Load duplicated w row into smem.
    {
        const float* wrow = w + (size_t)h * S_;
        for (int i = tid; i < 2048; i += 256) {
            float wv = (i < 2046) ? wrow[i] : 0.0f;
            wdup[i] = make_float2(wv, wv);
        }
    }

    // Thread tile: 4 j's (consecutive) x 8 d's (one 32B run -> 4 f32x2 pairs).
    const int d0    = (tid & 7) * 8;
    const int jbase = j0 + (tid >> 3) * 4;

    unsigned long long acc[4][4];
#pragma unroll
    for (int k = 0; k < 4; ++k)
#pragma unroll
        for (int p = 0; p < 4; ++p) acc[k][p] = 0ull;

    const size_t vrow_base = ((size_t)n * S_) * (H_ * D_) + (size_t)h * D_;

    for (int lc = 0; lc < S_; lc += TL) {
        __syncthreads();
        // Load v tile: 64 rows x 64 floats = 1024 float4, 4 per thread.
#pragma unroll
        for (int u = 0; u < 4; ++u) {
            int idx = tid + u * 256;
            int row = idx >> 4;          // 16 float4 per row
            int col = (idx & 15) * 4;
            int l   = lc + row;
            float4 val = *(const float4*)(v + vrow_base + (size_t)l * (H_ * D_) + col);
            if (l == 0 || l == S_ - 1) val = make_float4(0.f, 0.f, 0.f, 0.f);
            *(float4*)&vtile[row][col] = val;
        }
        __syncthreads();

#pragma unroll 8
        for (int i = 0; i < TL; ++i) {
            const int l = lc + i;
            const ulonglong2* vp = (const ulonglong2*)&vtile[i][d0];
            ulonglong2 va = vp[0];
            ulonglong2 vb = vp[1];
#pragma unroll
            for (int k = 0; k < 4; ++k) {
                int m = l - (jbase + k);
                m = (m < 0) ? -m : m;
                unsigned long long wk =
                    *(const unsigned long long*)&wdup[m];
                acc[k][0] = ffma2(wk, va.x, acc[k][0]);
                acc[k][1] = ffma2(wk, va.y, acc[k][1]);
                acc[k][2] = ffma2(wk, vb.x, acc[k][2]);
                acc[k][3] = ffma2(wk, vb.y, acc[k][3]);
            }
        }
    }

    // Store: out[((n*S + j)*H + h)*D + d]
#pragma unroll
    for (int k = 0; k < 4; ++k) {
        int j = jbase + k;
        unsigned long long a0 = acc[k][0], a1 = acc[k][1];
        unsigned long long a2 = acc[k][2], a3 = acc[k][3];
        if (j == 0 || j == S_ - 1) { a0 = a1 = a2 = a3 = 0ull; }
        float* dst = out + (((size_t)n * S_ + j) * H_ + h) * D_ + d0;
        ((ulonglong2*)dst)[0] = make_ulonglong2(a0, a1);
        ((ulonglong2*)dst)[1] = make_ulonglong2(a2, a3);
    }
}

__global__ void __launch_bounds__(256) zpb_kernel(
    const float* __restrict__ w, float* __restrict__ z)
{
    const int h = blockIdx.x;
    __shared__ float P[2048];     // P[t] = sum_{m=1}^{t} w[h,m], P[0]=0 (t used up to 2045)
    __shared__ float csum[256];

    const float* wrow = w + (size_t)h * S_;
    const int tid = threadIdx.x;

    // Per-thread local inclusive sums over 8 consecutive elements starting at 1+8*tid.
    float loc[8];
    float run = 0.f;
#pragma unroll
    for (int i = 0; i < 8; ++i) {
        int m = 1 + 8 * tid + i;
        float x = (m < 2046) ? wrow[m] : 0.f;
        run += x;
        loc[i] = run;
    }
    csum[tid] = run;
    __syncthreads();
    if (tid == 0) {
        float s = 0.f;
        for (int t = 0; t < 256; ++t) { float c = csum[t]; csum[t] = s; s += c; }
    }
    __syncthreads();
    float base = csum[tid];
#pragma unroll
    for (int i = 0; i < 8; ++i) {
        int t = 1 + 8 * tid + i;
        if (t < 2048) P[t] = base + loc[i];
    }
    if (tid == 0) P[0] = 0.f;
    __syncthreads();

    const float w0 = wrow[0];
    for (int j = tid; j < S_; j += 256) {
        float zv = (j == 0 || j == S_ - 1) ? 0.f : (w0 + P[j - 1] + P[2046 - j]);
        z[(size_t)j * H_ + h] = zv;
    }
}

extern "C" void kernel_launch(void* const* d_in, const int* in_sizes, int n_in,
                              void* d_out, int out_size) {
    const float* v = (const float*)d_in[0];
    const float* w = (const float*)d_in[1];
    if (n_in >= 2 && in_sizes[0] < in_sizes[1]) {  // safety: v is the big tensor
        const float* t = v; v = w; w = t;
    }
    float* out = (float*)d_out;
    float* z   = out + (size_t)B_ * S_ * H_ * D_;

    zpb_kernel<<<H_, 256>>>(w, z);
    dim3 grid(S_ / TJ, H_, B_);
    pbv_kernel<<<grid, 256>>>(v, w, out);
}

// round 3
// speedup vs baseline: 3.8048x; 3.8048x over previous
#include <cuda_runtime.h>
#include <cuda_bf16.h>
#include <cstdint>

// v (4, 2048, 12, 64) f32, w (12, 2048) f32.  seq_len = 2046.
// pbv[n,j,h,d] = sum_l w[h,|l-j|] * v[n,l,h,d], zero at j,l in {0,2047}
// z_pb[j,h]    = w[h,0] + P[j-1] + P[2046-j]
//
// pbv via warp-level mma.sync bf16 with fp32 emulation:
//   O = (Ah+Al)(Bh+Bl) ~= Ah*Bh + Ah*Bl + Al*Bh   (fp32 accum)
// A = bias tile, generated per-fragment in registers from smem w row.
// B = v chunk (64 l x 64 d) as bf16 hi/lo planes in smem, ldmatrix.x4.trans.

#define B_ 4
#define S_ 2048
#define H_ 12
#define D_ 64

__device__ __forceinline__ uint32_t smem_u32(const void* p) {
    uint32_t a;
    asm("{ .reg .u64 t; cvta.to.shared.u64 t, %1; cvt.u32.u64 %0, t; }"
        : "=r"(a) : "l"(p));
    return a;
}

// returns bf16x2 with 'lo' in the low half, 'hi' in the high half
__device__ __forceinline__ uint32_t pack_bf16x2(float lo, float hi) {
    uint32_t r;
    asm("cvt.rn.bf16x2.f32 %0, %1, %2;" : "=r"(r) : "f"(hi), "f"(lo));
    return r;
}
__device__ __forceinline__ float lo_of(uint32_t u) { return __uint_as_float(u << 16); }
__device__ __forceinline__ float hi_of(uint32_t u) { return __uint_as_float(u & 0xFFFF0000u); }

__device__ __forceinline__ void mma16816(float* c, const uint32_t* a, const uint32_t* b) {
    asm volatile(
        "mma.sync.aligned.m16n8k16.row.col.f32.bf16.bf16.f32 "
        "{%0,%1,%2,%3}, {%4,%5,%6,%7}, {%8,%9}, {%0,%1,%2,%3};"
        : "+f"(c[0]), "+f"(c[1]), "+f"(c[2]), "+f"(c[3])
        : "r"(a[0]), "r"(a[1]), "r"(a[2]), "r"(a[3]), "r"(b[0]), "r"(b[1]));
}

__device__ __forceinline__ void ldsm4t(uint32_t* r, uint32_t addr) {
    asm volatile(
        "ldmatrix.sync.aligned.m8n8.x4.trans.shared.b16 {%0,%1,%2,%3}, [%4];"
        : "=r"(r[0]), "=r"(r[1]), "=r"(r[2]), "=r"(r[3]) : "r"(addr));
}

__device__ __forceinline__ int iabs_(int x) { return x < 0 ? -x : x; }

__global__ void __launch_bounds__(256) pbv_mma_kernel(
    const float* __restrict__ v, const float* __restrict__ w,
    float* __restrict__ out)
{
    __shared__ float wsm[S_];
    __shared__ __align__(128) uint32_t vhi[64 * 32];   // 64 rows x 128B
    __shared__ __align__(128) uint32_t vlo[64 * 32];

    const int tid  = threadIdx.x;
    const int lane = tid & 31;
    const int wid  = tid >> 5;
    const int jt = blockIdx.x, h = blockIdx.y, n = blockIdx.z;
    const int j0 = jt * 128;

    // w row -> smem (zero-pad >= 2046)
    {
        const float* wrow = w + (size_t)h * S_;
        for (int i = tid; i < S_; i += 256)
            wsm[i] = (i < 2046) ? wrow[i] : 0.0f;
    }

    // fp32 accumulators: 8 n-tiles x 4
    float c[8][4];
#pragma unroll
    for (int t = 0; t < 8; ++t)
#pragma unroll
        for (int p = 0; p < 4; ++p) c[t][p] = 0.f;

    // v load mapping: thread -> (row in chunk, 16-float d segment)
    const int vr = tid >> 2;
    const int vd = (tid & 3) * 16;
    const float4* vsrc_base = (const float4*)(v +
        ((size_t)n * S_ * H_ + (size_t)h) * D_ + vd);
    // row l stride in float4s: H_*D_/4 = 192

    // ldmatrix per-lane mapping
    const int rb = lane & 15;          // k-row within 16
    const int co = lane >> 4;          // 0/1: low/high 8 n-cols
    const int xr = rb & 7;             // swizzle xor
    const uint32_t vhi_b = smem_u32(vhi);
    const uint32_t vlo_b = smem_u32(vlo);
    const uint32_t rowoff = (uint32_t)rb * 128u;

    // A-fragment mapping
    const int g = lane >> 2, q = lane & 3;
    const int jw = j0 + wid * 16;      // warp's first j row

    float4 pf0, pf1, pf2, pf3;
    {   // prefetch chunk 0
        const float4* src = vsrc_base + (size_t)vr * 192;
        pf0 = src[0]; pf1 = src[1]; pf2 = src[2]; pf3 = src[3];
    }

    for (int kc = 0; kc < 32; ++kc) {
        // ---- convert prefetched chunk to bf16 hi/lo planes ----
        {
            const int lg = kc * 64 + vr;
            const bool zl = (lg == 0) | (lg == S_ - 1);
            float f[16];
            f[0]=pf0.x; f[1]=pf0.y; f[2]=pf0.z; f[3]=pf0.w;
            f[4]=pf1.x; f[5]=pf1.y; f[6]=pf1.z; f[7]=pf1.w;
            f[8]=pf2.x; f[9]=pf2.y; f[10]=pf2.z; f[11]=pf2.w;
            f[12]=pf3.x; f[13]=pf3.y; f[14]=pf3.z; f[15]=pf3.w;
            if (zl) {
#pragma unroll
                for (int i = 0; i < 16; ++i) f[i] = 0.f;
            }
#pragma unroll
            for (int cchunk = 0; cchunk < 2; ++cchunk) {
                uint32_t uh[4], ul[4];
#pragma unroll
                for (int p = 0; p < 4; ++p) {
                    float x = f[cchunk * 8 + 2 * p];
                    float y = f[cchunk * 8 + 2 * p + 1];
                    uint32_t hpair = pack_bf16x2(x, y);
                    float rx = x - lo_of(hpair);
                    float ry = y - hi_of(hpair);
                    uh[p] = hpair;
                    ul[p] = pack_bf16x2(rx, ry);
                }
                int cc = (vd >> 3) + cchunk;
                int idx = vr * 32 + ((cc ^ (vr & 7)) << 2);
                *(uint4*)&vhi[idx] = make_uint4(uh[0], uh[1], uh[2], uh[3]);
                *(uint4*)&vlo[idx] = make_uint4(ul[0], ul[1], ul[2], ul[3]);
            }
        }
        __syncthreads();

        // ---- prefetch next chunk (hides DRAM latency behind MMA) ----
        if (kc < 31) {
            const float4* src = vsrc_base + (size_t)((kc + 1) * 64 + vr) * 192;
            pf0 = src[0]; pf1 = src[1]; pf2 = src[2]; pf3 = src[3];
        }

        const int lb = kc * 64;
#pragma unroll
        for (int s = 0; s < 4; ++s) {
            const int l0 = lb + s * 16;

            // ---- A fragments (hi/lo) from w row ----
            const int b0 = l0 + 2 * q - (jw + g);    // l - j for row g
            const int b1 = b0 - 8;                   // row g+8
            float w00 = wsm[iabs_(b0)],     w01 = wsm[iabs_(b0 + 1)];
            float w08 = wsm[iabs_(b0 + 8)], w09 = wsm[iabs_(b0 + 9)];
            float w10 = wsm[iabs_(b1)],     w11 = wsm[iabs_(b1 + 1)];
            float w18 = wsm[iabs_(b1 + 8)], w19 = wsm[iabs_(b1 + 9)];
            uint32_t ah[4], al[4];
            ah[0] = pack_bf16x2(w00, w01);
            ah[1] = pack_bf16x2(w10, w11);
            ah[2] = pack_bf16x2(w08, w09);
            ah[3] = pack_bf16x2(w18, w19);
            al[0] = pack_bf16x2(w00 - lo_of(ah[0]), w01 - hi_of(ah[0]));
            al[1] = pack_bf16x2(w10 - lo_of(ah[1]), w11 - hi_of(ah[1]));
            al[2] = pack_bf16x2(w08 - lo_of(ah[2]), w09 - hi_of(ah[2]));
            al[3] = pack_bf16x2(w18 - lo_of(ah[3]), w19 - hi_of(ah[3]));

            // ---- B fragments via ldmatrix.x4.trans ----
            uint32_t bh[16], bl[16];
            const uint32_t soff = (uint32_t)s * 2048u + rowoff;
#pragma unroll
            for (int t4 = 0; t4 < 4; ++t4) {
                uint32_t chunk = (uint32_t)((t4 * 2 + co) ^ xr);
                ldsm4t(&bh[t4 * 4], vhi_b + soff + chunk * 16u);
                ldsm4t(&bl[t4 * 4], vlo_b + soff + chunk * 16u);
            }

            // ---- 8 n-tiles x 3 emulation products ----
#pragma unroll
            for (int t = 0; t < 8; ++t) {
                const uint32_t* bhp = &bh[(t >> 1) * 4 + (t & 1) * 2];
                const uint32_t* blp = &bl[(t >> 1) * 4 + (t & 1) * 2];
                mma16816(c[t], ah, bhp);
                mma16816(c[t], ah, blp);
                mma16816(c[t], al, bhp);
            }
        }
        __syncthreads();
    }

    // ---- epilogue ----
    const int row0 = jw + g;
    const int row1 = jw + g + 8;
    const bool z0 = (row0 == 0) | (row0 == S_ - 1);
    const bool z1 = (row1 == 0) | (row1 == S_ - 1);
    float* o0 = out + ((size_t)(n * S_ + row0) * H_ + h) * D_ + q * 2;
    float* o1 = out + ((size_t)(n * S_ + row1) * H_ + h) * D_ + q * 2;
#pragma unroll
    for (int t = 0; t < 8; ++t) {
        float2 u0 = z0 ? make_float2(0.f, 0.f) : make_float2(c[t][0], c[t][1]);
        float2 u1 = z1 ? make_float2(0.f, 0.f) : make_float2(c[t][2], c[t][3]);
        *(float2*)(o0 + t * 8) = u0;
        *(float2*)(o1 + t * 8) = u1;
    }
}

__global__ void __launch_bounds__(256) zpb_kernel(
    const float* __restrict__ w, float* __restrict__ z)
{
    const int h = blockIdx.x;
    __shared__ float P[2048];
    __shared__ float csum[256];

    const float* wrow = w + (size_t)h * S_;
    const int tid = threadIdx.x;

    float loc[8];
    float run = 0.f;
#pragma unroll
    for (int i = 0; i < 8; ++i) {
        int m = 1 + 8 * tid + i;
        float x = (m < 2046) ? wrow[m] : 0.f;
        run += x;
        loc[i] = run;
    }
    csum[tid] = run;
    __syncthreads();
    if (tid == 0) {
        float s = 0.f;
        for (int t = 0; t < 256; ++t) { float cc = csum[t]; csum[t] = s; s += cc; }
    }
    __syncthreads();
    float base = csum[tid];
#pragma unroll
    for (int i = 0; i < 8; ++i) {
        int t = 1 + 8 * tid + i;
        if (t < 2048) P[t] = base + loc[i];
    }
    if (tid == 0) P[0] = 0.f;
    __syncthreads();

    const float w0 = wrow[0];
    for (int j = tid; j < S_; j += 256) {
        float zv = (j == 0 || j == S_ - 1) ? 0.f : (w0 + P[j - 1] + P[2046 - j]);
        z[(size_t)j * H_ + h] = zv;
    }
}

extern "C" void kernel_launch(void* const* d_in, const int* in_sizes, int n_in,
                              void* d_out, int out_size) {
    const float* v = (const float*)d_in[0];
    const float* w = (const float*)d_in[1];
    if (n_in >= 2 && in_sizes[0] < in_sizes[1]) {
        const float* t = v; v = w; w = t;
    }
    float* out = (float*)d_out;
    float* z   = out + (size_t)B_ * S_ * H_ * D_;

    zpb_kernel<<<H_, 256>>>(w, z);
    dim3 grid(S_ / 128, H_, B_);
    pbv_mma_kernel<<<grid, 256>>>(v, w, out);
}

// round 4
// speedup vs baseline: 4.1295x; 1.0854x over previous
#include <cuda_runtime.h>
#include <cuda_bf16.h>
#include <cstdint>

// v (4, 2048, 12, 64) f32, w (12, 2048) f32.  seq_len = 2046.
// pbv[n,j,h,d] = sum_l w[h,|l-j|] * v[n,l,h,d], zero at j,l in {0,2047}
// z_pb[j,h]    = w[h,0] + P[j-1] + P[2046-j]
//
// R4: mma.sync bf16 fp32-emulation (Ah*Bh + Ah*Bl + Al*Bh), with
//  - v pre-converted once to swizzled bf16 hi/lo chunk tiles in gmem scratch
//  - 3-stage cp.async ring, 1 __syncthreads per chunk
//  - per-CTA precomputed bf16-pair tables for A (bias) fragments

#define B_ 4
#define S_ 2048
#define H_ 12
#define D_ 64

// gmem scratch: 1536 chunks x (hi tile 2048 u32 + lo tile 2048 u32)
__device__ __align__(16) uint32_t g_vp[1536 * 4096];

// dynamic smem layout (bytes)
#define OFF_WHX 0
#define OFF_WLX 16384
#define OFF_BUF 32768
#define SM_TOTAL (32768 + 3 * 16384)   // 81920

__device__ __forceinline__ uint32_t smem_u32(const void* p) {
    uint32_t a;
    asm("{ .reg .u64 t; cvta.to.shared.u64 t, %1; cvt.u32.u64 %0, t; }"
        : "=r"(a) : "l"(p));
    return a;
}
// low half = first arg, high half = second arg
__device__ __forceinline__ uint32_t pack_bf16x2(float lo, float hi) {
    uint32_t r;
    asm("cvt.rn.bf16x2.f32 %0, %1, %2;" : "=r"(r) : "f"(hi), "f"(lo));
    return r;
}
__device__ __forceinline__ float lo_of(uint32_t u) { return __uint_as_float(u << 16); }
__device__ __forceinline__ float hi_of(uint32_t u) { return __uint_as_float(u & 0xFFFF0000u); }

__device__ __forceinline__ void mma16816(float* c, uint32_t a0, uint32_t a1,
                                         uint32_t a2, uint32_t a3,
                                         const uint32_t* b) {
    asm volatile(
        "mma.sync.aligned.m16n8k16.row.col.f32.bf16.bf16.f32 "
        "{%0,%1,%2,%3}, {%4,%5,%6,%7}, {%8,%9}, {%0,%1,%2,%3};"
        : "+f"(c[0]), "+f"(c[1]), "+f"(c[2]), "+f"(c[3])
        : "r"(a0), "r"(a1), "r"(a2), "r"(a3), "r"(b[0]), "r"(b[1]));
}
__device__ __forceinline__ void ldsm4t(uint32_t* r, uint32_t addr) {
    asm volatile(
        "ldmatrix.sync.aligned.m8n8.x4.trans.shared.b16 {%0,%1,%2,%3}, [%4];"
        : "=r"(r[0]), "=r"(r[1]), "=r"(r[2]), "=r"(r[3]) : "r"(addr));
}
__device__ __forceinline__ void cp16(uint32_t dst, const void* src) {
    asm volatile("cp.async.ca.shared.global [%0], [%1], 16;"
                 :: "r"(dst), "l"(src) : "memory");
}
__device__ __forceinline__ int iabs_(int x) { return x < 0 ? -x : x; }

// ---------------- pre-pass: v -> swizzled bf16 hi/lo chunk tiles ----------------
__global__ void __launch_bounds__(256) vconv_kernel(const float* __restrict__ v) {
    const int blk = blockIdx.x;         // (n*12+h)*32 + kc
    const int kc = blk & 31;
    const int nh = blk >> 5;
    const int h = nh % H_, n = nh / H_;
    const int tid = threadIdx.x;
    const int vr = tid >> 2;            // row in chunk 0..63
    const int cseg = tid & 3;           // 16-float segment
    const int l = kc * 64 + vr;

    const float4* src = (const float4*)(v +
        ((size_t)(n * S_ + l) * H_ + h) * D_ + cseg * 16);
    float4 p0 = src[0], p1 = src[1], p2 = src[2], p3 = src[3];
    float f[16];
    f[0]=p0.x; f[1]=p0.y; f[2]=p0.z; f[3]=p0.w;
    f[4]=p1.x; f[5]=p1.y; f[6]=p1.z; f[7]=p1.w;
    f[8]=p2.x; f[9]=p2.y; f[10]=p2.z; f[11]=p2.w;
    f[12]=p3.x; f[13]=p3.y; f[14]=p3.z; f[15]=p3.w;
    if (l == 0 || l == S_ - 1) {
#pragma unroll
        for (int i = 0; i < 16; ++i) f[i] = 0.f;
    }
    uint32_t* base = g_vp + (size_t)blk * 4096;
#pragma unroll
    for (int cchunk = 0; cchunk < 2; ++cchunk) {
        uint32_t uh[4], ul[4];
#pragma unroll
        for (int p = 0; p < 4; ++p) {
            float x = f[cchunk * 8 + 2 * p];
            float y = f[cchunk * 8 + 2 * p + 1];
            uint32_t hp = pack_bf16x2(x, y);
            uh[p] = hp;
            ul[p] = pack_bf16x2(x - lo_of(hp), y - hi_of(hp));
        }
        int cc = cseg * 2 + cchunk;
        int idx = vr * 32 + ((cc ^ (vr & 7)) << 2);
        *(uint4*)&base[idx]        = make_uint4(uh[0], uh[1], uh[2], uh[3]);
        *(uint4*)&base[2048 + idx] = make_uint4(ul[0], ul[1], ul[2], ul[3]);
    }
}

// ---------------- main kernel ----------------
__global__ void __launch_bounds__(256) pbv_mma_kernel(
    const float* __restrict__ w, float* __restrict__ out)
{
    extern __shared__ char smem[];
    uint32_t* whx = (uint32_t*)(smem + OFF_WHX);
    uint32_t* wlx = (uint32_t*)(smem + OFF_WLX);

    const int tid  = threadIdx.x;
    const int lane = tid & 31;
    const int wid  = tid >> 5;
    const int jt = blockIdx.x, h = blockIdx.y, n = blockIdx.z;
    const int j0 = jt * 128;
    const int nh32 = (n * H_ + h) * 32;

    // ---- build A pair tables: whx/wlx[i] = pairs of bf16 hi/lo of wext(i-2048) ----
    {
        uint32_t* tmp = (uint32_t*)(smem + OFF_BUF);  // reuse buf0 area
        const float* wrow = w + (size_t)h * S_;
        for (int i = tid; i < 4096; i += 256) {
            int m = iabs_(i - 2048);
            float e = (m < 2046) ? wrow[m] : 0.f;
            uint32_t ph = pack_bf16x2(e, 0.f);           // low16 = bf16(e)
            float r = e - __uint_as_float(ph << 16);
            uint32_t pl = pack_bf16x2(r, 0.f);
            tmp[i] = (ph << 16) | (pl & 0xFFFFu);        // top=hi bits, low=lo bits
        }
        __syncthreads();
        uint32_t mine[16];
#pragma unroll
        for (int u = 0; u < 16; ++u) {
            int i = tid + u * 256;
            uint32_t a = tmp[i];
            uint32_t b = (i < 4095) ? tmp[i + 1] : 0u;
            mine[u] = a;             // stash; write after sync since tmp aliases buf0
            mine[u] = 0;             // (unused placeholder to keep shape)
            // compute directly:
            whx[i] = (a >> 16) | (b & 0xFFFF0000u);
            wlx[i] = (a & 0xFFFFu) | (b << 16);
        }
        (void)mine;
        __syncthreads();
    }

    const uint32_t sb = smem_u32(smem);
    const uint32_t bufb0 = sb + OFF_BUF;

    // ---- preload chunks 0,1 ----
#pragma unroll
    for (int pc = 0; pc < 2; ++pc) {
        const char* src = (const char*)(g_vp + (size_t)(nh32 + pc) * 4096) + tid * 16;
        uint32_t dst = bufb0 + pc * 16384 + tid * 16;
#pragma unroll
        for (int i = 0; i < 4; ++i)
            cp16(dst + i * 4096, src + i * 4096);
        asm volatile("cp.async.commit_group;" ::: "memory");
    }

    // accumulators
    float c[8][4];
#pragma unroll
    for (int t = 0; t < 8; ++t)
#pragma unroll
        for (int p = 0; p < 4; ++p) c[t][p] = 0.f;

    // ldmatrix lane mapping
    const int rb = lane & 15;
    const int co = lane >> 4;
    const int xr = rb & 7;
    const uint32_t rowoff = (uint32_t)rb * 128u;

    // A fragment mapping
    const int g = lane >> 2, q = lane & 3;
    const int jw = j0 + wid * 16;
    const int qg = 2 * q - (jw + g) + 2048;

    for (int kc = 0; kc < 32; ++kc) {
        asm volatile("cp.async.wait_group 1;" ::: "memory");
        __syncthreads();

        // issue loads for chunk kc+2
        if (kc + 2 < 32) {
            const char* src = (const char*)(g_vp + (size_t)(nh32 + kc + 2) * 4096) + tid * 16;
            uint32_t dst = bufb0 + ((kc + 2) % 3) * 16384 + tid * 16;
#pragma unroll
            for (int i = 0; i < 4; ++i)
                cp16(dst + i * 4096, src + i * 4096);
        }
        asm volatile("cp.async.commit_group;" ::: "memory");

        const uint32_t vhi_b = bufb0 + (kc % 3) * 16384;
        const uint32_t vlo_b = vhi_b + 8192;

#pragma unroll
        for (int s = 0; s < 4; ++s) {
            const int i0 = qg + kc * 64 + s * 16;
            uint32_t ah0 = whx[i0], ah1 = whx[i0 - 8], ah2 = whx[i0 + 8];
            uint32_t al0 = wlx[i0], al1 = wlx[i0 - 8], al2 = wlx[i0 + 8];

            uint32_t bh[16], bl[16];
            const uint32_t soff = (uint32_t)s * 2048u + rowoff;
#pragma unroll
            for (int t4 = 0; t4 < 4; ++t4) {
                uint32_t chunk = (uint32_t)((t4 * 2 + co) ^ xr);
                ldsm4t(&bh[t4 * 4], vhi_b + soff + chunk * 16u);
                ldsm4t(&bl[t4 * 4], vlo_b + soff + chunk * 16u);
            }
#pragma unroll
            for (int t = 0; t < 8; ++t) {
                const uint32_t* bhp = &bh[(t >> 1) * 4 + (t & 1) * 2];
                const uint32_t* blp = &bl[(t >> 1) * 4 + (t & 1) * 2];
                mma16816(c[t], ah0, ah1, ah2, ah0, bhp);
                mma16816(c[t], ah0, ah1, ah2, ah0, blp);
                mma16816(c[t], al0, al1, al2, al0, bhp);
            }
        }
    }

    // ---- epilogue ----
    const int row0 = jw + g;
    const int row1 = jw + g + 8;
    const bool z0 = (row0 == 0) | (row0 == S_ - 1);
    const bool z1 = (row1 == 0) | (row1 == S_ - 1);
    float* o0 = out + ((size_t)(n * S_ + row0) * H_ + h) * D_ + q * 2;
    float* o1 = out + ((size_t)(n * S_ + row1) * H_ + h) * D_ + q * 2;
#pragma unroll
    for (int t = 0; t < 8; ++t) {
        float2 u0 = z0 ? make_float2(0.f, 0.f) : make_float2(c[t][0], c[t][1]);
        float2 u1 = z1 ? make_float2(0.f, 0.f) : make_float2(c[t][2], c[t][3]);
        *(float2*)(o0 + t * 8) = u0;
        *(float2*)(o1 + t * 8) = u1;
    }
}

// ---------------- z_pb ----------------
__global__ void __launch_bounds__(256) zpb_kernel(
    const float* __restrict__ w, float* __restrict__ z)
{
    const int h = blockIdx.x;
    __shared__ float P[2048];
    __shared__ float csum[256];

    const float* wrow = w + (size_t)h * S_;
    const int tid = threadIdx.x;

    float loc[8];
    float run = 0.f;
#pragma unroll
    for (int i = 0; i < 8; ++i) {
        int m = 1 + 8 * tid + i;
        float x = (m < 2046) ? wrow[m] : 0.f;
        run += x;
        loc[i] = run;
    }
    csum[tid] = run;
    __syncthreads();
    if (tid == 0) {
        float s = 0.f;
        for (int t = 0; t < 256; ++t) { float cc = csum[t]; csum[t] = s; s += cc; }
    }
    __syncthreads();
    float base = csum[tid];
#pragma unroll
    for (int i = 0; i < 8; ++i) {
        int t = 1 + 8 * tid + i;
        if (t < 2048) P[t] = base + loc[i];
    }
    if (tid == 0) P[0] = 0.f;
    __syncthreads();

    const float w0 = wrow[0];
    for (int j = tid; j < S_; j += 256) {
        float zv = (j == 0 || j == S_ - 1) ? 0.f : (w0 + P[j - 1] + P[2046 - j]);
        z[(size_t)j * H_ + h] = zv;
    }
}

extern "C" void kernel_launch(void* const* d_in, const int* in_sizes, int n_in,
                              void* d_out, int out_size) {
    const float* v = (const float*)d_in[0];
    const float* w = (const float*)d_in[1];
    if (n_in >= 2 && in_sizes[0] < in_sizes[1]) {
        const float* t = v; v = w; w = t;
    }
    float* out = (float*)d_out;
    float* z   = out + (size_t)B_ * S_ * H_ * D_;

    cudaFuncSetAttribute(pbv_mma_kernel,
                         cudaFuncAttributeMaxDynamicSharedMemorySize, SM_TOTAL);

    zpb_kernel<<<H_, 256>>>(w, z);
    vconv_kernel<<<B_ * H_ * 32, 256>>>(v);
    dim3 grid(S_ / 128, H_, B_);
    pbv_mma_kernel<<<grid, 256, SM_TOTAL>>>(w, out);
}

// round 5
// speedup vs baseline: 6.0694x; 1.4698x over previous
#include <cuda_runtime.h>
#include <cuda_fp16.h>
#include <cstdint>

// v (4, 2048, 12, 64) f32, w (12, 2048) f32.  seq_len = 2046.
// pbv[n,j,h,d] = sum_l w[h,|l-j|] * v[n,l,h,d], zero at j,l in {0,2047}
// z_pb[j,h]    = w[h,0] + P[j-1] + P[2046-j]
//
// R5: fp16 2-product emulation: O = Ah*B + Al*B
//   A = w split hi/lo fp16 (pair tables in smem, ~22-bit effective)
//   B = v rounded once to fp16 (error ~2^-12, well under 1e-3)
//  - v pre-converted once to swizzled fp16 chunk tiles in gmem scratch
//  - 3-stage cp.async ring, 1 __syncthreads per chunk

#define B_ 4
#define S_ 2048
#define H_ 12
#define D_ 64

// gmem scratch: 1536 chunks x (64 rows x 64 fp16 = 2048 u32)
__device__ __align__(16) uint32_t g_vp[1536 * 2048];

// dynamic smem layout (bytes)
#define OFF_WHX 0
#define OFF_WLX 16384
#define OFF_BUF 32768
#define SM_TOTAL (32768 + 3 * 8192)   // 57344

__device__ __forceinline__ uint32_t smem_u32(const void* p) {
    uint32_t a;
    asm("{ .reg .u64 t; cvta.to.shared.u64 t, %1; cvt.u32.u64 %0, t; }"
        : "=r"(a) : "l"(p));
    return a;
}
__device__ __forceinline__ void mma16816(float* c, uint32_t a0, uint32_t a1,
                                         uint32_t a2, uint32_t a3,
                                         const uint32_t* b) {
    asm volatile(
        "mma.sync.aligned.m16n8k16.row.col.f32.f16.f16.f32 "
        "{%0,%1,%2,%3}, {%4,%5,%6,%7}, {%8,%9}, {%0,%1,%2,%3};"
        : "+f"(c[0]), "+f"(c[1]), "+f"(c[2]), "+f"(c[3])
        : "r"(a0), "r"(a1), "r"(a2), "r"(a3), "r"(b[0]), "r"(b[1]));
}
__device__ __forceinline__ void ldsm4t(uint32_t* r, uint32_t addr) {
    asm volatile(
        "ldmatrix.sync.aligned.m8n8.x4.trans.shared.b16 {%0,%1,%2,%3}, [%4];"
        : "=r"(r[0]), "=r"(r[1]), "=r"(r[2]), "=r"(r[3]) : "r"(addr));
}
__device__ __forceinline__ void cp16(uint32_t dst, const void* src) {
    asm volatile("cp.async.ca.shared.global [%0], [%1], 16;"
                 :: "r"(dst), "l"(src) : "memory");
}
__device__ __forceinline__ int iabs_(int x) { return x < 0 ? -x : x; }
__device__ __forceinline__ uint32_t f16bits(float x) {
    __half_raw hr = __half_raw(__float2half_rn(x));
    return (uint32_t)hr.x;
}
__device__ __forceinline__ float f16val(uint32_t bits) {
    __half_raw hr; hr.x = (unsigned short)bits;
    return __half2float(__half(hr));
}

// ---------------- pre-pass: v -> swizzled fp16 chunk tiles ----------------
__global__ void __launch_bounds__(256) vconv_kernel(const float* __restrict__ v) {
    const int blk = blockIdx.x;         // (n*12+h)*32 + kc
    const int kc = blk & 31;
    const int nh = blk >> 5;
    const int h = nh % H_, n = nh / H_;
    const int tid = threadIdx.x;
    const int vr = tid >> 2;            // row in chunk 0..63
    const int cseg = tid & 3;           // 16-float segment
    const int l = kc * 64 + vr;

    const float4* src = (const float4*)(v +
        ((size_t)(n * S_ + l) * H_ + h) * D_ + cseg * 16);
    float4 p0 = src[0], p1 = src[1], p2 = src[2], p3 = src[3];
    float f[16];
    f[0]=p0.x; f[1]=p0.y; f[2]=p0.z; f[3]=p0.w;
    f[4]=p1.x; f[5]=p1.y; f[6]=p1.z; f[7]=p1.w;
    f[8]=p2.x; f[9]=p2.y; f[10]=p2.z; f[11]=p2.w;
    f[12]=p3.x; f[13]=p3.y; f[14]=p3.z; f[15]=p3.w;
    if (l == 0 || l == S_ - 1) {
#pragma unroll
        for (int i = 0; i < 16; ++i) f[i] = 0.f;
    }
    uint32_t* base = g_vp + (size_t)blk * 2048;
#pragma unroll
    for (int cchunk = 0; cchunk < 2; ++cchunk) {
        uint32_t u[4];
#pragma unroll
        for (int p = 0; p < 4; ++p) {
            __half2 hp = __floats2half2_rn(f[cchunk * 8 + 2 * p],
                                           f[cchunk * 8 + 2 * p + 1]);
            u[p] = *(uint32_t*)&hp;
        }
        int cc = cseg * 2 + cchunk;
        int idx = vr * 32 + ((cc ^ (vr & 7)) << 2);
        *(uint4*)&base[idx] = make_uint4(u[0], u[1], u[2], u[3]);
    }
}

// ---------------- main kernel ----------------
__global__ void __launch_bounds__(256) pbv_mma_kernel(
    const float* __restrict__ w, float* __restrict__ out)
{
    extern __shared__ char smem[];
    uint32_t* whx = (uint32_t*)(smem + OFF_WHX);
    uint32_t* wlx = (uint32_t*)(smem + OFF_WLX);

    const int tid  = threadIdx.x;
    const int lane = tid & 31;
    const int wid  = tid >> 5;
    const int jt = blockIdx.x, h = blockIdx.y, n = blockIdx.z;
    const int j0 = jt * 128;
    const int nh32 = (n * H_ + h) * 32;

    // ---- build A pair tables: whx/wlx[i] = fp16 pairs of wext(i-2048), wext(i-2047) ----
    {
        uint32_t* tmp = (uint32_t*)(smem + OFF_BUF);  // reuse ring buffers (24KB >= 16KB)
        const float* wrow = w + (size_t)h * S_;
        for (int i = tid; i < 4096; i += 256) {
            int m = iabs_(i - 2048);
            float e = (m < 2046) ? wrow[m] : 0.f;
            uint32_t hb = f16bits(e);
            float r = e - f16val(hb);
            uint32_t lb = f16bits(r);
            tmp[i] = (hb << 16) | lb;      // top = hi bits, low = lo bits
        }
        __syncthreads();
        for (int i = tid; i < 4096; i += 256) {
            uint32_t a = tmp[i];
            uint32_t b = (i < 4095) ? tmp[i + 1] : 0u;
            whx[i] = (a >> 16) | (b & 0xFFFF0000u);    // pair of hi-halves
            wlx[i] = (a & 0xFFFFu) | (b << 16);        // pair of lo-halves
        }
        __syncthreads();
    }

    const uint32_t sb = smem_u32(smem);
    const uint32_t bufb0 = sb + OFF_BUF;

    // ---- preload chunks 0,1 (8KB each: 32B per thread) ----
#pragma unroll
    for (int pc = 0; pc < 2; ++pc) {
        const char* src = (const char*)(g_vp + (size_t)(nh32 + pc) * 2048) + tid * 16;
        uint32_t dst = bufb0 + pc * 8192 + tid * 16;
        cp16(dst, src);
        cp16(dst + 4096, src + 4096);
        asm volatile("cp.async.commit_group;" ::: "memory");
    }

    // accumulators
    float c[8][4];
#pragma unroll
    for (int t = 0; t < 8; ++t)
#pragma unroll
        for (int p = 0; p < 4; ++p) c[t][p] = 0.f;

    // ldmatrix lane mapping
    const int rb = lane & 15;
    const int co = lane >> 4;
    const int xr = rb & 7;
    const uint32_t rowoff = (uint32_t)rb * 128u;

    // A fragment mapping
    const int g = lane >> 2, q = lane & 3;
    const int jw = j0 + wid * 16;
    const int qg = 2 * q - (jw + g) + 2048;

    for (int kc = 0; kc < 32; ++kc) {
        asm volatile("cp.async.wait_group 1;" ::: "memory");
        __syncthreads();

        // issue loads for chunk kc+2
        if (kc + 2 < 32) {
            const char* src = (const char*)(g_vp + (size_t)(nh32 + kc + 2) * 2048) + tid * 16;
            uint32_t dst = bufb0 + ((kc + 2) % 3) * 8192 + tid * 16;
            cp16(dst, src);
            cp16(dst + 4096, src + 4096);
        }
        asm volatile("cp.async.commit_group;" ::: "memory");

        const uint32_t vb = bufb0 + (kc % 3) * 8192;

#pragma unroll
        for (int s = 0; s < 4; ++s) {
            const int i0 = qg + kc * 64 + s * 16;
            uint32_t ah0 = whx[i0], ah1 = whx[i0 - 8], ah2 = whx[i0 + 8];
            uint32_t al0 = wlx[i0], al1 = wlx[i0 - 8], al2 = wlx[i0 + 8];

            uint32_t bh[16];
            const uint32_t soff = (uint32_t)s * 2048u + rowoff;
#pragma unroll
            for (int t4 = 0; t4 < 4; ++t4) {
                uint32_t chunk = (uint32_t)((t4 * 2 + co) ^ xr);
                ldsm4t(&bh[t4 * 4], vb + soff + chunk * 16u);
            }
#pragma unroll
            for (int t = 0; t < 8; ++t) {
                const uint32_t* bhp = &bh[(t >> 1) * 4 + (t & 1) * 2];
                mma16816(c[t], ah0, ah1, ah2, ah0, bhp);  // Toeplitz: a3 == a0
                mma16816(c[t], al0, al1, al2, al0, bhp);
            }
        }
    }

    // ---- epilogue ----
    const int row0 = jw + g;
    const int row1 = jw + g + 8;
    const bool z0 = (row0 == 0) | (row0 == S_ - 1);
    const bool z1 = (row1 == 0) | (row1 == S_ - 1);
    float* o0 = out + ((size_t)(n * S_ + row0) * H_ + h) * D_ + q * 2;
    float* o1 = out + ((size_t)(n * S_ + row1) * H_ + h) * D_ + q * 2;
#pragma unroll
    for (int t = 0; t < 8; ++t) {
        float2 u0 = z0 ? make_float2(0.f, 0.f) : make_float2(c[t][0], c[t][1]);
        float2 u1 = z1 ? make_float2(0.f, 0.f) : make_float2(c[t][2], c[t][3]);
        *(float2*)(o0 + t * 8) = u0;
        *(float2*)(o1 + t * 8) = u1;
    }
}

// ---------------- z_pb ----------------
__global__ void __launch_bounds__(256) zpb_kernel(
    const float* __restrict__ w, float* __restrict__ z)
{
    const int h = blockIdx.x;
    __shared__ float P[2048];
    __shared__ float csum[256];

    const float* wrow = w + (size_t)h * S_;
    const int tid = threadIdx.x;

    float loc[8];
    float run = 0.f;
#pragma unroll
    for (int i = 0; i < 8; ++i) {
        int m = 1 + 8 * tid + i;
        float x = (m < 2046) ? wrow[m] : 0.f;
        run += x;
        loc[i] = run;
    }
    csum[tid] = run;
    __syncthreads();
    if (tid == 0) {
        float s = 0.f;
        for (int t = 0; t < 256; ++t) { float cc = csum[t]; csum[t] = s; s += cc; }
    }
    __syncthreads();
    float base = csum[tid];
#pragma unroll
    for (int i = 0; i < 8; ++i) {
        int t = 1 + 8 * tid + i;
        if (t < 2048) P[t] = base + loc[i];
    }
    if (tid == 0) P[0] = 0.f;
    __syncthreads();

    const float w0 = wrow[0];
    for (int j = tid; j < S_; j += 256) {
        float zv = (j == 0 || j == S_ - 1) ? 0.f : (w0 + P[j - 1] + P[2046 - j]);
        z[(size_t)j * H_ + h] = zv;
    }
}

extern "C" void kernel_launch(void* const* d_in, const int* in_sizes, int n_in,
                              void* d_out, int out_size) {
    const float* v = (const float*)d_in[0];
    const float* w = (const float*)d_in[1];
    if (n_in >= 2 && in_sizes[0] < in_sizes[1]) {
        const float* t = v; v = w; w = t;
    }
    float* out = (float*)d_out;
    float* z   = out + (size_t)B_ * S_ * H_ * D_;

    cudaFuncSetAttribute(pbv_mma_kernel,
                         cudaFuncAttributeMaxDynamicSharedMemorySize, SM_TOTAL);

    zpb_kernel<<<H_, 256>>>(w, z);
    vconv_kernel<<<B_ * H_ * 32, 256>>>(v);
    dim3 grid(S_ / 128, H_, B_);
    pbv_mma_kernel<<<grid, 256, SM_TOTAL>>>(w, out);
}

// round 6
// speedup vs baseline: 9.2189x; 1.5189x over previous
#include <cuda_runtime.h>
#include <cuda_fp16.h>
#include <cstdint>

// v (4, 2048, 12, 64) f32, w (12, 2048) f32.  seq_len = 2046.
// pbv[n,j,h,d] = sum_l w[h,|l-j|] * v[n,l,h,d], zero at j,l in {0,2047}
// z_pb[j,h]    = w[h,0] + P[j-1] + P[2046-j]
//
// R6: single fp16 product O = fp16(A)*fp16(B)  (err ~3-4e-4 < 1e-3)
//  - v pre-converted once to swizzled fp16 chunk tiles in gmem scratch
//  - zpb fused into the pre-pass kernel (block-index switch)
//  - 3-stage cp.async ring, 1 __syncthreads per chunk
//  - A (bias) fragments from a per-CTA fp16-pair table (3 LDS per k16-step)

#define B_ 4
#define S_ 2048
#define H_ 12
#define D_ 64

// gmem scratch: 1536 chunks x (64 rows x 64 fp16 = 2048 u32)
__device__ __align__(16) uint32_t g_vp[1536 * 2048];

// dynamic smem layout (bytes)
#define OFF_WHX 0
#define OFF_BUF 16384
#define SM_TOTAL (16384 + 3 * 8192)   // 40960

__device__ __forceinline__ uint32_t smem_u32(const void* p) {
    uint32_t a;
    asm("{ .reg .u64 t; cvta.to.shared.u64 t, %1; cvt.u32.u64 %0, t; }"
        : "=r"(a) : "l"(p));
    return a;
}
__device__ __forceinline__ void mma16816(float* c, uint32_t a0, uint32_t a1,
                                         uint32_t a2, uint32_t a3,
                                         const uint32_t* b) {
    asm volatile(
        "mma.sync.aligned.m16n8k16.row.col.f32.f16.f16.f32 "
        "{%0,%1,%2,%3}, {%4,%5,%6,%7}, {%8,%9}, {%0,%1,%2,%3};"
        : "+f"(c[0]), "+f"(c[1]), "+f"(c[2]), "+f"(c[3])
        : "r"(a0), "r"(a1), "r"(a2), "r"(a3), "r"(b[0]), "r"(b[1]));
}
__device__ __forceinline__ void ldsm4t(uint32_t* r, uint32_t addr) {
    asm volatile(
        "ldmatrix.sync.aligned.m8n8.x4.trans.shared.b16 {%0,%1,%2,%3}, [%4];"
        : "=r"(r[0]), "=r"(r[1]), "=r"(r[2]), "=r"(r[3]) : "r"(addr));
}
__device__ __forceinline__ void cp16(uint32_t dst, const void* src) {
    asm volatile("cp.async.ca.shared.global [%0], [%1], 16;"
                 :: "r"(dst), "l"(src) : "memory");
}
__device__ __forceinline__ int iabs_(int x) { return x < 0 ? -x : x; }
__device__ __forceinline__ uint32_t f16bits(float x) {
    __half_raw hr = __half_raw(__float2half_rn(x));
    return (uint32_t)hr.x;
}

// ---------------- fused pre-pass: vconv (blocks 0..1535) + zpb (blocks 1536..1547) ----
__global__ void __launch_bounds__(256) pre_kernel(
    const float* __restrict__ v, const float* __restrict__ w,
    float* __restrict__ z)
{
    __shared__ float P[2048];
    __shared__ float csum[256];
    const int tid = threadIdx.x;

    if (blockIdx.x < 1536) {
        // ---- v -> swizzled fp16 chunk tiles ----
        const int blk = blockIdx.x;       // (n*12+h)*32 + kc
        const int kc = blk & 31;
        const int nh = blk >> 5;
        const int h = nh % H_, n = nh / H_;
        const int vr = tid >> 2;          // row in chunk 0..63
        const int cseg = tid & 3;         // 16-float segment
        const int l = kc * 64 + vr;

        const float4* src = (const float4*)(v +
            ((size_t)(n * S_ + l) * H_ + h) * D_ + cseg * 16);
        float4 p0 = src[0], p1 = src[1], p2 = src[2], p3 = src[3];
        float f[16];
        f[0]=p0.x; f[1]=p0.y; f[2]=p0.z; f[3]=p0.w;
        f[4]=p1.x; f[5]=p1.y; f[6]=p1.z; f[7]=p1.w;
        f[8]=p2.x; f[9]=p2.y; f[10]=p2.z; f[11]=p2.w;
        f[12]=p3.x; f[13]=p3.y; f[14]=p3.z; f[15]=p3.w;
        if (l == 0 || l == S_ - 1) {
#pragma unroll
            for (int i = 0; i < 16; ++i) f[i] = 0.f;
        }
        uint32_t* base = g_vp + (size_t)blk * 2048;
#pragma unroll
        for (int cchunk = 0; cchunk < 2; ++cchunk) {
            uint32_t u[4];
#pragma unroll
            for (int p = 0; p < 4; ++p) {
                __half2 hp = __floats2half2_rn(f[cchunk * 8 + 2 * p],
                                               f[cchunk * 8 + 2 * p + 1]);
                u[p] = *(uint32_t*)&hp;
            }
            int cc = cseg * 2 + cchunk;
            int idx = vr * 32 + ((cc ^ (vr & 7)) << 2);
            *(uint4*)&base[idx] = make_uint4(u[0], u[1], u[2], u[3]);
        }
        return;
    }

    // ---- z_pb for head h ----
    const int h = blockIdx.x - 1536;
    const float* wrow = w + (size_t)h * S_;

    float loc[8];
    float run = 0.f;
#pragma unroll
    for (int i = 0; i < 8; ++i) {
        int m = 1 + 8 * tid + i;
        float x = (m < 2046) ? wrow[m] : 0.f;
        run += x;
        loc[i] = run;
    }
    csum[tid] = run;
    __syncthreads();
    if (tid == 0) {
        float s = 0.f;
        for (int t = 0; t < 256; ++t) { float cc = csum[t]; csum[t] = s; s += cc; }
    }
    __syncthreads();
    float base = csum[tid];
#pragma unroll
    for (int i = 0; i < 8; ++i) {
        int t = 1 + 8 * tid + i;
        if (t < 2048) P[t] = base + loc[i];
    }
    if (tid == 0) P[0] = 0.f;
    __syncthreads();

    const float w0 = wrow[0];
    for (int j = tid; j < S_; j += 256) {
        float zv = (j == 0 || j == S_ - 1) ? 0.f : (w0 + P[j - 1] + P[2046 - j]);
        z[(size_t)j * H_ + h] = zv;
    }
}

// ---------------- main kernel ----------------
__global__ void __launch_bounds__(256) pbv_mma_kernel(
    const float* __restrict__ w, float* __restrict__ out)
{
    extern __shared__ char smem[];
    uint32_t* whx = (uint32_t*)(smem + OFF_WHX);

    const int tid  = threadIdx.x;
    const int lane = tid & 31;
    const int wid  = tid >> 5;
    const int jt = blockIdx.x, h = blockIdx.y, n = blockIdx.z;
    const int j0 = jt * 128;
    const int nh32 = (n * H_ + h) * 32;

    // ---- build A pair table: whx[i] = fp16 pair (wext(i-2048), wext(i-2047)) ----
    {
        uint32_t* tmp = (uint32_t*)(smem + OFF_BUF);  // reuse ring buffers (24KB >= 16KB)
        const float* wrow = w + (size_t)h * S_;
        for (int i = tid; i < 4096; i += 256) {
            int m = iabs_(i - 2048);
            float e = (m < 2046) ? wrow[m] : 0.f;
            tmp[i] = f16bits(e);
        }
        __syncthreads();
        for (int i = tid; i < 4096; i += 256) {
            uint32_t a = tmp[i];
            uint32_t b = (i < 4095) ? tmp[i + 1] : 0u;
            whx[i] = a | (b << 16);
        }
        __syncthreads();
    }

    const uint32_t sb = smem_u32(smem);
    const uint32_t bufb0 = sb + OFF_BUF;

    // ---- preload chunks 0,1 (8KB each: 32B per thread) ----
#pragma unroll
    for (int pc = 0; pc < 2; ++pc) {
        const char* src = (const char*)(g_vp + (size_t)(nh32 + pc) * 2048) + tid * 16;
        uint32_t dst = bufb0 + pc * 8192 + tid * 16;
        cp16(dst, src);
        cp16(dst + 4096, src + 4096);
        asm volatile("cp.async.commit_group;" ::: "memory");
    }

    // accumulators
    float c[8][4];
#pragma unroll
    for (int t = 0; t < 8; ++t)
#pragma unroll
        for (int p = 0; p < 4; ++p) c[t][p] = 0.f;

    // ldmatrix lane mapping
    const int rb = lane & 15;
    const int co = lane >> 4;
    const int xr = rb & 7;
    const uint32_t rowoff = (uint32_t)rb * 128u;

    // A fragment mapping
    const int g = lane >> 2, q = lane & 3;
    const int jw = j0 + wid * 16;
    const int qg = 2 * q - (jw + g) + 2048;

    for (int kc = 0; kc < 32; ++kc) {
        asm volatile("cp.async.wait_group 1;" ::: "memory");
        __syncthreads();

        // issue loads for chunk kc+2
        if (kc + 2 < 32) {
            const char* src = (const char*)(g_vp + (size_t)(nh32 + kc + 2) * 2048) + tid * 16;
            uint32_t dst = bufb0 + ((kc + 2) % 3) * 8192 + tid * 16;
            cp16(dst, src);
            cp16(dst + 4096, src + 4096);
        }
        asm volatile("cp.async.commit_group;" ::: "memory");

        const uint32_t vb = bufb0 + (kc % 3) * 8192;

#pragma unroll
        for (int s = 0; s < 4; ++s) {
            const int i0 = qg + kc * 64 + s * 16;
            uint32_t ah0 = whx[i0], ah1 = whx[i0 - 8], ah2 = whx[i0 + 8];

            uint32_t bh[16];
            const uint32_t soff = (uint32_t)s * 2048u + rowoff;
#pragma unroll
            for (int t4 = 0; t4 < 4; ++t4) {
                uint32_t chunk = (uint32_t)((t4 * 2 + co) ^ xr);
                ldsm4t(&bh[t4 * 4], vb + soff + chunk * 16u);
            }
#pragma unroll
            for (int t = 0; t < 8; ++t) {
                const uint32_t* bhp = &bh[(t >> 1) * 4 + (t & 1) * 2];
                mma16816(c[t], ah0, ah1, ah2, ah0, bhp);  // Toeplitz: a3 == a0
            }
        }
    }

    // ---- epilogue ----
    const int row0 = jw + g;
    const int row1 = jw + g + 8;
    const bool z0 = (row0 == 0) | (row0 == S_ - 1);
    const bool z1 = (row1 == 0) | (row1 == S_ - 1);
    float* o0 = out + ((size_t)(n * S_ + row0) * H_ + h) * D_ + q * 2;
    float* o1 = out + ((size_t)(n * S_ + row1) * H_ + h) * D_ + q * 2;
#pragma unroll
    for (int t = 0; t < 8; ++t) {
        float2 u0 = z0 ? make_float2(0.f, 0.f) : make_float2(c[t][0], c[t][1]);
        float2 u1 = z1 ? make_float2(0.f, 0.f) : make_float2(c[t][2], c[t][3]);
        *(float2*)(o0 + t * 8) = u0;
        *(float2*)(o1 + t * 8) = u1;
    }
}

extern "C" void kernel_launch(void* const* d_in, const int* in_sizes, int n_in,
                              void* d_out, int out_size) {
    const float* v = (const float*)d_in[0];
    const float* w = (const float*)d_in[1];
    if (n_in >= 2 && in_sizes[0] < in_sizes[1]) {
        const float* t = v; v = w; w = t;
    }
    float* out = (float*)d_out;
    float* z   = out + (size_t)B_ * S_ * H_ * D_;

    cudaFuncSetAttribute(pbv_mma_kernel,
                         cudaFuncAttributeMaxDynamicSharedMemorySize, SM_TOTAL);

    pre_kernel<<<1536 + H_, 256>>>(v, w, z);
    dim3 grid(S_ / 128, H_, B_);
    pbv_mma_kernel<<<grid, 256, SM_TOTAL>>>(w, out);
}

// round 7
// speedup vs baseline: 11.2204x; 1.2171x over previous
#include <cuda_runtime.h>
#include <cuda_fp16.h>
#include <cstdint>

// v (4, 2048, 12, 64) f32, w (12, 2048) f32.  seq_len = 2046.
// pbv[n,j,h,d] = sum_l w[h,|l-j|] * v[n,l,h,d], zero at j,l in {0,2047}
// z_pb[j,h]    = w[h,0] + P[j-1] + P[2046-j]
//
// R7: single fp16 product O = fp16(A)*fp16(B); 4 warps x 32 j-rows (2 m-tiles
// per warp -> B fragments reused twice, LDSM traffic halved). A-pair table
// built once per head in the pre-pass; main kernel cp.asyncs it in.

#define B_ 4
#define S_ 2048
#define H_ 12
#define D_ 64

// gmem scratch
__device__ __align__(16) uint32_t g_vp[1536 * 2048];  // v fp16 chunk tiles
__device__ __align__(16) uint32_t g_wh[H_ * 4096];    // per-head A pair table

// dynamic smem layout (bytes)
#define OFF_WHX 0
#define OFF_BUF 16384
#define SM_TOTAL (16384 + 3 * 8192)   // 40960

__device__ __forceinline__ uint32_t smem_u32(const void* p) {
    uint32_t a;
    asm("{ .reg .u64 t; cvta.to.shared.u64 t, %1; cvt.u32.u64 %0, t; }"
        : "=r"(a) : "l"(p));
    return a;
}
__device__ __forceinline__ void mma16816(float* c, uint32_t a0, uint32_t a1,
                                         uint32_t a2, uint32_t a3,
                                         const uint32_t* b) {
    asm volatile(
        "mma.sync.aligned.m16n8k16.row.col.f32.f16.f16.f32 "
        "{%0,%1,%2,%3}, {%4,%5,%6,%7}, {%8,%9}, {%0,%1,%2,%3};"
        : "+f"(c[0]), "+f"(c[1]), "+f"(c[2]), "+f"(c[3])
        : "r"(a0), "r"(a1), "r"(a2), "r"(a3), "r"(b[0]), "r"(b[1]));
}
__device__ __forceinline__ void ldsm4t(uint32_t* r, uint32_t addr) {
    asm volatile(
        "ldmatrix.sync.aligned.m8n8.x4.trans.shared.b16 {%0,%1,%2,%3}, [%4];"
        : "=r"(r[0]), "=r"(r[1]), "=r"(r[2]), "=r"(r[3]) : "r"(addr));
}
__device__ __forceinline__ void cp16(uint32_t dst, const void* src) {
    asm volatile("cp.async.cg.shared.global [%0], [%1], 16;"
                 :: "r"(dst), "l"(src) : "memory");
}
__device__ __forceinline__ int iabs_(int x) { return x < 0 ? -x : x; }
__device__ __forceinline__ uint32_t f16bits(float x) {
    __half_raw hr = __half_raw(__float2half_rn(x));
    return (uint32_t)hr.x;
}

// ------- pre-pass: vconv (0..1535) + zpb (1536..1547) + A tables (1548..1559) ----
__global__ void __launch_bounds__(256) pre_kernel(
    const float* __restrict__ v, const float* __restrict__ w,
    float* __restrict__ z)
{
    __shared__ float P[2048];
    __shared__ float csum[256];
    const int tid = threadIdx.x;

    if (blockIdx.x < 1536) {
        // ---- v -> swizzled fp16 chunk tiles ----
        const int blk = blockIdx.x;       // (n*12+h)*32 + kc
        const int kc = blk & 31;
        const int nh = blk >> 5;
        const int h = nh % H_, n = nh / H_;
        const int vr = tid >> 2;          // row in chunk 0..63
        const int cseg = tid & 3;         // 16-float segment
        const int l = kc * 64 + vr;

        const float4* src = (const float4*)(v +
            ((size_t)(n * S_ + l) * H_ + h) * D_ + cseg * 16);
        float4 p0 = src[0], p1 = src[1], p2 = src[2], p3 = src[3];
        float f[16];
        f[0]=p0.x; f[1]=p0.y; f[2]=p0.z; f[3]=p0.w;
        f[4]=p1.x; f[5]=p1.y; f[6]=p1.z; f[7]=p1.w;
        f[8]=p2.x; f[9]=p2.y; f[10]=p2.z; f[11]=p2.w;
        f[12]=p3.x; f[13]=p3.y; f[14]=p3.z; f[15]=p3.w;
        if (l == 0 || l == S_ - 1) {
#pragma unroll
            for (int i = 0; i < 16; ++i) f[i] = 0.f;
        }
        uint32_t* base = g_vp + (size_t)blk * 2048;
#pragma unroll
        for (int cchunk = 0; cchunk < 2; ++cchunk) {
            uint32_t u[4];
#pragma unroll
            for (int p = 0; p < 4; ++p) {
                __half2 hp = __floats2half2_rn(f[cchunk * 8 + 2 * p],
                                               f[cchunk * 8 + 2 * p + 1]);
                u[p] = *(uint32_t*)&hp;
            }
            int cc = cseg * 2 + cchunk;
            int idx = vr * 32 + ((cc ^ (vr & 7)) << 2);
            *(uint4*)&base[idx] = make_uint4(u[0], u[1], u[2], u[3]);
        }
        return;
    }

    if (blockIdx.x >= 1548) {
        // ---- A pair table for head h: g_wh[h][i] = f16 pair (wext(i-2048), wext(i-2047)) ----
        const int h = blockIdx.x - 1548;
        const float* wrow = w + (size_t)h * S_;
        uint32_t* dst = g_wh + (size_t)h * 4096;
        for (int i = tid; i < 4096; i += 256) {
            int m0 = iabs_(i - 2048);
            int m1 = iabs_(i - 2047);
            float e0 = (m0 < 2046) ? wrow[m0] : 0.f;
            float e1 = (m1 < 2046) ? wrow[m1] : 0.f;
            dst[i] = f16bits(e0) | (f16bits(e1) << 16);
        }
        return;
    }

    // ---- z_pb for head h ----
    const int h = blockIdx.x - 1536;
    const float* wrow = w + (size_t)h * S_;

    float loc[8];
    float run = 0.f;
#pragma unroll
    for (int i = 0; i < 8; ++i) {
        int m = 1 + 8 * tid + i;
        float x = (m < 2046) ? wrow[m] : 0.f;
        run += x;
        loc[i] = run;
    }
    csum[tid] = run;
    __syncthreads();
    if (tid == 0) {
        float s = 0.f;
        for (int t = 0; t < 256; ++t) { float cc = csum[t]; csum[t] = s; s += cc; }
    }
    __syncthreads();
    float base = csum[tid];
#pragma unroll
    for (int i = 0; i < 8; ++i) {
        int t = 1 + 8 * tid + i;
        if (t < 2048) P[t] = base + loc[i];
    }
    if (tid == 0) P[0] = 0.f;
    __syncthreads();

    const float w0 = wrow[0];
    for (int j = tid; j < S_; j += 256) {
        float zv = (j == 0 || j == S_ - 1) ? 0.f : (w0 + P[j - 1] + P[2046 - j]);
        z[(size_t)j * H_ + h] = zv;
    }
}

// ---------------- main kernel: 128 threads, 4 warps x 32 j-rows ----------------
__global__ void __launch_bounds__(128) pbv_mma_kernel(float* __restrict__ out)
{
    extern __shared__ char smem[];
    uint32_t* whx = (uint32_t*)(smem + OFF_WHX);

    const int tid  = threadIdx.x;
    const int lane = tid & 31;
    const int wid  = tid >> 5;
    const int jt = blockIdx.x, h = blockIdx.y, n = blockIdx.z;
    const int j0 = jt * 128;
    const int nh32 = (n * H_ + h) * 32;

    const uint32_t sb = smem_u32(smem);
    const uint32_t bufb0 = sb + OFF_BUF;

    // ---- preload: A table (16KB) + chunk0 in group0; chunk1 in group1 ----
    {
        const char* tsrc = (const char*)(g_wh + (size_t)h * 4096) + tid * 16;
        uint32_t tdst = sb + OFF_WHX + tid * 16;
#pragma unroll
        for (int i = 0; i < 8; ++i)
            cp16(tdst + i * 2048, tsrc + i * 2048);
        const char* src = (const char*)(g_vp + (size_t)nh32 * 2048) + tid * 16;
        uint32_t dst = bufb0 + tid * 16;
#pragma unroll
        for (int i = 0; i < 4; ++i)
            cp16(dst + i * 2048, src + i * 2048);
        asm volatile("cp.async.commit_group;" ::: "memory");
        const char* src1 = (const char*)(g_vp + (size_t)(nh32 + 1) * 2048) + tid * 16;
        uint32_t dst1 = bufb0 + 8192 + tid * 16;
#pragma unroll
        for (int i = 0; i < 4; ++i)
            cp16(dst1 + i * 2048, src1 + i * 2048);
        asm volatile("cp.async.commit_group;" ::: "memory");
    }

    // accumulators: 2 m-tiles x 8 n-tiles x 4
    float c[2][8][4];
#pragma unroll
    for (int m = 0; m < 2; ++m)
#pragma unroll
        for (int t = 0; t < 8; ++t)
#pragma unroll
            for (int p = 0; p < 4; ++p) c[m][t][p] = 0.f;

    // ldmatrix lane mapping
    const int rb = lane & 15;
    const int co = lane >> 4;
    const int xr = rb & 7;
    const uint32_t rowoff = (uint32_t)rb * 128u;

    // A fragment mapping: warp covers j rows [jw, jw+32)
    const int g = lane >> 2, q = lane & 3;
    const int jw = j0 + wid * 32;
    const int qg = 2 * q - (jw + g) + 2048;

    for (int kc = 0; kc < 32; ++kc) {
        asm volatile("cp.async.wait_group 1;" ::: "memory");
        __syncthreads();

        // issue loads for chunk kc+2
        if (kc + 2 < 32) {
            const char* src = (const char*)(g_vp + (size_t)(nh32 + kc + 2) * 2048) + tid * 16;
            uint32_t dst = bufb0 + ((kc + 2) % 3) * 8192 + tid * 16;
#pragma unroll
            for (int i = 0; i < 4; ++i)
                cp16(dst + i * 2048, src + i * 2048);
        }
        asm volatile("cp.async.commit_group;" ::: "memory");

        const uint32_t vb = bufb0 + (kc % 3) * 8192;

#pragma unroll
        for (int s = 0; s < 4; ++s) {
            const int i0 = qg + kc * 64 + s * 16;
            // 5 LDS cover both m-tiles (Toeplitz shift reuse)
            uint32_t wp8 = whx[i0 + 8], w0 = whx[i0], wm8 = whx[i0 - 8];
            uint32_t wm16 = whx[i0 - 16], wm24 = whx[i0 - 24];

            uint32_t bh[16];
            const uint32_t soff = (uint32_t)s * 2048u + rowoff;
#pragma unroll
            for (int t4 = 0; t4 < 4; ++t4) {
                uint32_t chunk = (uint32_t)((t4 * 2 + co) ^ xr);
                ldsm4t(&bh[t4 * 4], vb + soff + chunk * 16u);
            }
#pragma unroll
            for (int t = 0; t < 8; ++t) {
                const uint32_t* bhp = &bh[(t >> 1) * 4 + (t & 1) * 2];
                mma16816(c[0][t], w0, wm8, wp8, w0, bhp);     // rows jw..jw+15
                mma16816(c[1][t], wm16, wm24, wm8, wm16, bhp); // rows jw+16..jw+31
            }
        }
    }

    // ---- epilogue ----
#pragma unroll
    for (int m = 0; m < 2; ++m) {
        const int row0 = jw + m * 16 + g;
        const int row1 = row0 + 8;
        const bool z0 = (row0 == 0) | (row0 == S_ - 1);
        const bool z1 = (row1 == 0) | (row1 == S_ - 1);
        float* o0 = out + ((size_t)(n * S_ + row0) * H_ + h) * D_ + q * 2;
        float* o1 = out + ((size_t)(n * S_ + row1) * H_ + h) * D_ + q * 2;
#pragma unroll
        for (int t = 0; t < 8; ++t) {
            float2 u0 = z0 ? make_float2(0.f, 0.f)
                           : make_float2(c[m][t][0], c[m][t][1]);
            float2 u1 = z1 ? make_float2(0.f, 0.f)
                           : make_float2(c[m][t][2], c[m][t][3]);
            *(float2*)(o0 + t * 8) = u0;
            *(float2*)(o1 + t * 8) = u1;
        }
    }
}

extern "C" void kernel_launch(void* const* d_in, const int* in_sizes, int n_in,
                              void* d_out, int out_size) {
    const float* v = (const float*)d_in[0];
    const float* w = (const float*)d_in[1];
    if (n_in >= 2 && in_sizes[0] < in_sizes[1]) {
        const float* t = v; v = w; w = t;
    }
    float* out = (float*)d_out;
    float* z   = out + (size_t)B_ * S_ * H_ * D_;

    cudaFuncSetAttribute(pbv_mma_kernel,
                         cudaFuncAttributeMaxDynamicSharedMemorySize, SM_TOTAL);

    pre_kernel<<<1536 + 2 * H_, 256>>>(v, w, z);
    dim3 grid(S_ / 128, H_, B_);
    pbv_mma_kernel<<<grid, 128, SM_TOTAL>>>(out);
}